// round 1
// baseline (speedup 1.0000x reference)
#include <cuda_runtime.h>

#define NPTS   16384
#define TPB    256
#define QPT    16
#define NPAIR  (QPT / 2)
#define QBLKS  (NPTS / (TPB * QPT))   // 4
#define RBLKS  18
#define RCHUNK 912                     // 18 * 912 = 16416 >= 16384

typedef unsigned long long ull;

// Per-query best (min d^2) as int-reinterpreted positive floats. 2 directions.
__device__ int g_best[2 * NPTS];

// ---------------- f32x2 packed helpers (sm_103a) ----------------
__device__ __forceinline__ ull f2_fma(ull a, ull b, ull c) {
    ull d; asm("fma.rn.f32x2 %0, %1, %2, %3;" : "=l"(d) : "l"(a), "l"(b), "l"(c)); return d;
}
__device__ __forceinline__ ull f2_add(ull a, ull b) {
    ull d; asm("add.rn.f32x2 %0, %1, %2;" : "=l"(d) : "l"(a), "l"(b)); return d;
}
__device__ __forceinline__ ull f2_pack(float lo, float hi) {
    ull d; asm("mov.b64 %0, {%1, %2};" : "=l"(d) : "f"(lo), "f"(hi)); return d;
}
__device__ __forceinline__ void f2_unpack(float& lo, float& hi, ull v) {
    asm("mov.b64 {%0, %1}, %2;" : "=f"(lo), "=f"(hi) : "l"(v));
}

// ---------------- kernels ----------------
__global__ void init_kernel() {
    int i = blockIdx.x * blockDim.x + threadIdx.x;
    if (i < 2 * NPTS) g_best[i] = 0x7F7FFFFF;  // FLT_MAX bits
}

__global__ __launch_bounds__(TPB) void nn_kernel(const float* __restrict__ pred,
                                                 const float* __restrict__ gt) {
    // Per ref point: 4 duplicated-packed f32x2 coeffs: (-2x,-2x)(-2y,-2y)(-2z,-2z)(n,n)
    __shared__ ull s_ref[RCHUNK * 4];

    const int dir = blockIdx.z;
    const float* __restrict__ qp = (dir == 0) ? pred : gt;
    const float* __restrict__ rp = (dir == 0) ? gt : pred;

    const int rbase = blockIdx.y * RCHUNK;
    const int rcnt = min(RCHUNK, NPTS - rbase);

    // Cooperative load of the ref tile, pre-negated / pre-duplicated.
    for (int j = threadIdx.x; j < rcnt; j += TPB) {
        const float x = rp[(rbase + j) * 3 + 0];
        const float y = rp[(rbase + j) * 3 + 1];
        const float z = rp[(rbase + j) * 3 + 2];
        const float n = x * x + y * y + z * z;
        s_ref[j * 4 + 0] = f2_pack(-2.0f * x, -2.0f * x);
        s_ref[j * 4 + 1] = f2_pack(-2.0f * y, -2.0f * y);
        s_ref[j * 4 + 2] = f2_pack(-2.0f * z, -2.0f * z);
        s_ref[j * 4 + 3] = f2_pack(n, n);
    }

    // Each thread owns 16 queries = 8 packed f32x2 lanes (stride TPB for coalescing).
    const int q0 = blockIdx.x * (TPB * QPT) + threadIdx.x;
    ull qx2[NPAIR], qy2[NPAIR], qz2[NPAIR], qn2[NPAIR];
    float best[QPT];
    #pragma unroll
    for (int p = 0; p < NPAIR; p++) {
        const int qa = q0 + (2 * p) * TPB;
        const int qb = q0 + (2 * p + 1) * TPB;
        const float ax = qp[qa * 3 + 0], ay = qp[qa * 3 + 1], az = qp[qa * 3 + 2];
        const float bx = qp[qb * 3 + 0], by = qp[qb * 3 + 1], bz = qp[qb * 3 + 2];
        qx2[p] = f2_pack(ax, bx);
        qy2[p] = f2_pack(ay, by);
        qz2[p] = f2_pack(az, bz);
        qn2[p] = f2_pack(ax * ax + ay * ay + az * az,
                         bx * bx + by * by + bz * bz);
        best[2 * p]     = 3.4e38f;
        best[2 * p + 1] = 3.4e38f;
    }
    __syncthreads();

    // Main sweep: d2 = qn + n - 2 q.r  (expanded form, matching reference numerics).
    const ulonglong2* __restrict__ s2 = (const ulonglong2*)s_ref;
    for (int j = 0; j < rcnt; j++) {
        const ulonglong2 v0 = s2[j * 2 + 0];   // a2, b2
        const ulonglong2 v1 = s2[j * 2 + 1];   // c2, n2
        const ull a2 = v0.x, b2 = v0.y, c2 = v1.x, n2 = v1.y;
        #pragma unroll
        for (int p = 0; p < NPAIR; p++) {
            ull acc = f2_add(qn2[p], n2);
            acc = f2_fma(qx2[p], a2, acc);
            acc = f2_fma(qy2[p], b2, acc);
            acc = f2_fma(qz2[p], c2, acc);
            float lo, hi;
            f2_unpack(lo, hi, acc);
            best[2 * p]     = fminf(best[2 * p], lo);
            best[2 * p + 1] = fminf(best[2 * p + 1], hi);
        }
    }

    // Merge partial mins (positive floats => int compare == float compare).
    int* gb = g_best + dir * NPTS;
    #pragma unroll
    for (int p = 0; p < NPAIR; p++) {
        atomicMin(&gb[q0 + (2 * p) * TPB],     __float_as_int(best[2 * p]));
        atomicMin(&gb[q0 + (2 * p + 1) * TPB], __float_as_int(best[2 * p + 1]));
    }
}

__global__ void reduce_kernel(const float* __restrict__ weight, float* __restrict__ out) {
    __shared__ float s0s[512], s1s[512];
    const int t = threadIdx.x;
    float s0 = 0.0f, s1 = 0.0f;
    for (int i = t; i < NPTS; i += 512) {
        s0 += __int_as_float(g_best[i]);
        s1 += __int_as_float(g_best[NPTS + i]);
    }
    s0s[t] = s0; s1s[t] = s1;
    __syncthreads();
    for (int s = 256; s > 0; s >>= 1) {
        if (t < s) { s0s[t] += s0s[t + s]; s1s[t] += s1s[t + s]; }
        __syncthreads();
    }
    if (t == 0) {
        const float w = weight[0];
        const float inv = 1.0f / (3.0f * (float)NPTS);
        out[0] = w * s0s[0] * inv + (1.0f - w) * s1s[0] * inv;
    }
}

extern "C" void kernel_launch(void* const* d_in, const int* in_sizes, int n_in,
                              void* d_out, int out_size) {
    const float* pred   = (const float*)d_in[0];
    const float* gt     = (const float*)d_in[1];
    const float* weight = (const float*)d_in[2];
    float* out = (float*)d_out;
    (void)in_sizes; (void)n_in; (void)out_size;

    init_kernel<<<(2 * NPTS + 255) / 256, 256>>>();
    nn_kernel<<<dim3(QBLKS, RBLKS, 2), TPB>>>(pred, gt);
    reduce_kernel<<<1, 512>>>(weight, out);
}